// round 2
// baseline (speedup 1.0000x reference)
#include <cuda_runtime.h>
#include <cstdint>

#define BATCH   8
#define GH      64
#define C0      64
#define NPTS    16384
#define NFREQ   10
#define HID     256
#define P       64
#define SROW    260
#define KC      16
#define K0PAD   240

// ---------------- device scratch (static, allocation-free) ----------------
__device__ float g_gamma[BATCH * HID];
__device__ float g_beta [BATCH * HID];
__device__ float g_W0p  [K0PAD * HID];
__device__ float g_lvl1 [BATCH * 32 * 32 * C0];
__device__ float g_lvl2 [BATCH * 16 * 16 * C0];

// ---------------- helpers ----------------
__device__ __forceinline__ float gelu_f(float x) {
    float x3 = x * x * x;
    float t  = tanhf(0.7978845608028654f * (x + 0.044715f * x3));
    return 0.5f * x * (1.0f + t);
}

__device__ __forceinline__ unsigned long long dup_f32x2(float a) {
    unsigned long long r;
    asm("mov.b64 %0, {%1, %1};" : "=l"(r) : "f"(a));
    return r;
}

__device__ __forceinline__ void fma_f32x2(unsigned long long& d,
                                          unsigned long long a,
                                          unsigned long long b) {
    asm("fma.rn.f32x2 %0, %1, %2, %0;" : "+l"(d) : "l"(a), "l"(b));
}

__device__ __forceinline__ void cp16(uint32_t saddr, const float* g) {
    asm volatile("cp.async.cg.shared.global [%0], [%1], 16;" :: "r"(saddr), "l"(g));
}

// ---------------- prep: FiLM params ----------------
__global__ void prep_ctx_kernel(const float* __restrict__ cv,
                                const float* __restrict__ Wc,
                                const float* __restrict__ bc) {
    int b = blockIdx.x, c = threadIdx.x;
    float g  = bc[c];
    float bt = bc[HID + c];
#pragma unroll 8
    for (int k = 0; k < C0; k++) {
        float v = cv[b * C0 + k];
        g  += v * Wc[k * 2 * HID + c];
        bt += v * Wc[k * 2 * HID + HID + c];
    }
    g_gamma[b * HID + c] = g + 1.0f;
    g_beta [b * HID + c] = bt;
}

// ---------------- prep: pad W0 (234 rows) -> 240 rows, with a 2-row gap
// inserted at row 42 so that feature columns start 16B-aligned in smem.
__global__ void prep_w0_kernel(const float* __restrict__ W0) {
    int r = blockIdx.x, c = threadIdx.x;
    float v = 0.0f;
    if (r < 42)                  v = W0[r * HID + c];
    else if (r >= 44 && r < 236) v = W0[(r - 2) * HID + c];
    g_W0p[r * HID + c] = v;
}

// ---------------- prep: antialiased bilinear pyramid (jax.image.resize) ----
template <int HL>
__global__ void resize_kernel(const float* __restrict__ src) {
    int idx = blockIdx.x * blockDim.x + threadIdx.x;
    int c = idx & (C0 - 1);
    int v = idx >> 6;
    int x = v % HL;
    int y = (v / HL) % HL;
    int b = v / (HL * HL);

    const float scale = (float)(GH / HL);   // 2 or 4
    const int   T     = 2 * (GH / HL);      // taps per dim

    float sy = (y + 0.5f) * scale - 0.5f;
    float sx = (x + 0.5f) * scale - 0.5f;
    int s0y = (int)floorf(sy - scale) + 1;  // ceil(sy - scale)
    int s0x = (int)floorf(sx - scale) + 1;

    float wy[8], wx[8];
    float sumy = 0.f, sumx = 0.f;
#pragma unroll
    for (int t = 0; t < T; t++) {
        int s = s0y + t;
        float w = 1.0f - fabsf((float)s - sy) / scale;
        w = (s >= 0 && s < GH && w > 0.f) ? w : 0.f;
        wy[t] = w; sumy += w;
        s = s0x + t;
        w = 1.0f - fabsf((float)s - sx) / scale;
        w = (s >= 0 && s < GH && w > 0.f) ? w : 0.f;
        wx[t] = w; sumx += w;
    }
    float inv = 1.0f / (sumy * sumx);

    float acc = 0.f;
#pragma unroll
    for (int a = 0; a < T; a++) {
        if (wy[a] == 0.f) continue;
        const float* row = src + ((((b * GH) + (s0y + a)) * GH) << 6) + c;
        float pacc = 0.f;
#pragma unroll
        for (int t = 0; t < T; t++) {
            if (wx[t] == 0.f) continue;
            pacc += wx[t] * row[(s0x + t) << 6];
        }
        acc += wy[a] * pacc;
    }
    float* dst = (HL == 32) ? g_lvl1 : g_lvl2;
    dst[idx] = acc * inv;
}

// ---------------- main fused decoder ----------------
__global__ __launch_bounds__(256, 2)
void decoder_kernel(const float* __restrict__ fg,
                    const float* __restrict__ coords,
                    const float* __restrict__ b0,
                    const float* __restrict__ W1, const float* __restrict__ b1,
                    const float* __restrict__ W2, const float* __restrict__ b2,
                    const float* __restrict__ W3, const float* __restrict__ b3,
                    const float* __restrict__ Wout, const float* __restrict__ bout,
                    float* __restrict__ out) {
    extern __shared__ float smem[];
    float* h_s  = smem;                   // P * SROW   (h tile, [point][col])
    float* w_s  = h_s + P * SROW;         // 2 * KC * HID (weight double buffer)
    float* wo_s = w_s + 2 * KC * HID;     // 3 * HID    (Wout)
    float* bo_s = wo_s + 3 * HID;         // 4          (bout)

    const int tid = threadIdx.x;
    const int b   = blockIdx.x >> 8;
    const int n0  = (blockIdx.x & 255) * P;

    // stage Wout / bout
    for (int i = tid; i < 3 * HID; i += 256) wo_s[i] = Wout[i];
    if (tid < 3) bo_s[tid] = bout[tid];

    // ---- build h tile: posenc + 3-level bilinear samples ----
    {
        int p = tid >> 2, q = tid & 3;
        float cy = coords[(n0 + p) * 2 + 0];
        float cx = coords[(n0 + p) * 2 + 1];

        if (q == 0) {
            float* hp = h_s + p * SROW;
            hp[0] = cy; hp[1] = cx;
            float fr = 3.14159265358979323846f;
#pragma unroll
            for (int f = 0; f < NFREQ; f++) {
                float sv, cvv;
                sincosf(cy * fr, &sv, &cvv);
                hp[2 + 4 * f + 0] = sv;
                hp[2 + 4 * f + 2] = cvv;
                sincosf(cx * fr, &sv, &cvv);
                hp[2 + 4 * f + 1] = sv;
                hp[2 + 4 * f + 3] = cvv;
                fr *= 2.0f;
            }
            // zero padded columns (gap at 42..43, tail 236..239)
            hp[42] = 0.f; hp[43] = 0.f;
            hp[236] = 0.f; hp[237] = 0.f; hp[238] = 0.f; hp[239] = 0.f;
        }

#pragma unroll
        for (int lvl = 0; lvl < 3; lvl++) {
            int Hl = GH >> lvl;
            const float* G = (lvl == 0) ? fg : ((lvl == 1) ? g_lvl1 : g_lvl2);
            float yf = (cy + 1.0f) * 0.5f * (float)(Hl - 1);
            float xf = (cx + 1.0f) * 0.5f * (float)(Hl - 1);
            float y0f = floorf(yf), x0f = floorf(xf);
            float wy = yf - y0f, wx = xf - x0f;
            int y0 = min(max((int)y0f, 0), Hl - 1);
            int x0 = min(max((int)x0f, 0), Hl - 1);
            int y1 = min(y0 + 1, Hl - 1);
            int x1 = min(x0 + 1, Hl - 1);
            const float* p00 = G + ((((b * Hl) + y0) * Hl + x0) << 6);
            const float* p01 = G + ((((b * Hl) + y0) * Hl + x1) << 6);
            const float* p10 = G + ((((b * Hl) + y1) * Hl + x0) << 6);
            const float* p11 = G + ((((b * Hl) + y1) * Hl + x1) << 6);
            float omx = 1.0f - wx, omy = 1.0f - wy;
            float* dst = h_s + p * SROW + 44 + lvl * 64 + q * 16;
#pragma unroll
            for (int cc = 0; cc < 4; cc++) {
                int c = q * 16 + cc * 4;
                float4 v00 = *(const float4*)(p00 + c);
                float4 v01 = *(const float4*)(p01 + c);
                float4 v10 = *(const float4*)(p10 + c);
                float4 v11 = *(const float4*)(p11 + c);
                float4 r;
                r.x = (v00.x * omx + v01.x * wx) * omy + (v10.x * omx + v11.x * wx) * wy;
                r.y = (v00.y * omx + v01.y * wx) * omy + (v10.y * omx + v11.y * wx) * wy;
                r.z = (v00.z * omx + v01.z * wx) * omy + (v10.z * omx + v11.z * wx) * wy;
                r.w = (v00.w * omx + v01.w * wx) * omy + (v10.w * omx + v11.w * wx) * wy;
                *(float4*)(dst + cc * 4) = r;
            }
        }
    }
    __syncthreads();

    // ---- 4 FiLM'd MLP layers, chunked SGEMM with f32x2 FMAs ----
    const int tx = tid & 31, ty = tid >> 5;
    const int cb = tx * 8;
    const float* Wptrs[4] = {g_W0p, W1, W2, W3};
    const float* bptrs[4] = {b0, b1, b2, b3};
    const float* gam = g_gamma + b * HID;
    const float* bet = g_beta  + b * HID;

    for (int l = 0; l < 4; l++) {
        const float* Wl = Wptrs[l];
        const int NCH = (l == 0) ? (K0PAD / KC) : (HID / KC);

        unsigned long long acc[8][4];
#pragma unroll
        for (int i = 0; i < 8; i++)
#pragma unroll
            for (int j = 0; j < 4; j++) acc[i][j] = 0ull;

        // prefetch chunk 0
        {
            const float* gsrc = Wl;
            uint32_t sb = (uint32_t)__cvta_generic_to_shared(w_s);
#pragma unroll
            for (int s = 0; s < 4; s++) {
                int f = tid + s * 256;
                cp16(sb + f * 16, gsrc + f * 4);
            }
            asm volatile("cp.async.commit_group;");
        }

        for (int ch = 0; ch < NCH; ch++) {
            if (ch + 1 < NCH) {
                const float* gsrc = Wl + (ch + 1) * (KC * HID);
                uint32_t sb = (uint32_t)__cvta_generic_to_shared(
                    w_s + ((ch + 1) & 1) * (KC * HID));
#pragma unroll
                for (int s = 0; s < 4; s++) {
                    int f = tid + s * 256;
                    cp16(sb + f * 16, gsrc + f * 4);
                }
                asm volatile("cp.async.commit_group;");
                asm volatile("cp.async.wait_group 1;");
            } else {
                asm volatile("cp.async.wait_group 0;");
            }
            __syncthreads();

            const float* wb = w_s + (ch & 1) * (KC * HID);
            const int kg0 = ch * KC;
#pragma unroll
            for (int kk = 0; kk < KC; kk += 2) {
                float2 a2[8];
#pragma unroll
                for (int i = 0; i < 8; i++)
                    a2[i] = *(const float2*)&h_s[(ty * 8 + i) * SROW + kg0 + kk];
#pragma unroll
                for (int u = 0; u < 2; u++) {
                    const float* wr = wb + (kk + u) * HID + cb;
                    ulonglong2 bA = *(const ulonglong2*)wr;
                    ulonglong2 bB = *(const ulonglong2*)(wr + 4);
                    unsigned long long bp0 = bA.x, bp1 = bA.y, bp2 = bB.x, bp3 = bB.y;
#pragma unroll
                    for (int i = 0; i < 8; i++) {
                        float av = (u == 0) ? a2[i].x : a2[i].y;
                        unsigned long long ad = dup_f32x2(av);
                        fma_f32x2(acc[i][0], ad, bp0);
                        fma_f32x2(acc[i][1], ad, bp1);
                        fma_f32x2(acc[i][2], ad, bp2);
                        fma_f32x2(acc[i][3], ad, bp3);
                    }
                }
            }
            __syncthreads();   // protect w_s buffer before it is re-filled
        }

        // activation: bias + FiLM + gelu, write back transposed-in-place
        float bias[8], ga[8], be[8];
        *(float4*)&bias[0] = *(const float4*)(bptrs[l] + cb);
        *(float4*)&bias[4] = *(const float4*)(bptrs[l] + cb + 4);
        *(float4*)&ga[0]   = *(const float4*)(gam + cb);
        *(float4*)&ga[4]   = *(const float4*)(gam + cb + 4);
        *(float4*)&be[0]   = *(const float4*)(bet + cb);
        *(float4*)&be[4]   = *(const float4*)(bet + cb + 4);

#pragma unroll
        for (int i = 0; i < 8; i++) {
            float o[8];
#pragma unroll
            for (int j4 = 0; j4 < 4; j4++) {
                float lo, hi;
                asm("mov.b64 {%0, %1}, %2;" : "=f"(lo), "=f"(hi) : "l"(acc[i][j4]));
                o[2 * j4] = lo; o[2 * j4 + 1] = hi;
            }
#pragma unroll
            for (int j = 0; j < 8; j++) {
                float v = (o[j] + bias[j]) * ga[j] + be[j];
                o[j] = gelu_f(v);
            }
            float* dst = h_s + (ty * 8 + i) * SROW + cb;
            *(float4*)dst       = make_float4(o[0], o[1], o[2], o[3]);
            *(float4*)(dst + 4) = make_float4(o[4], o[5], o[6], o[7]);
        }
        __syncthreads();
    }

    // ---- output head: tanh(h @ Wout + bout) ----
    if (tid < 192) {
        int p = tid & 63, o = tid >> 6;
        float acc = bo_s[o];
        const float* hp = h_s + p * SROW;
#pragma unroll 8
        for (int k = 0; k < HID; k++) acc += hp[k] * wo_s[k * 3 + o];
        out[((size_t)b * NPTS + n0 + p) * 3 + o] = tanhf(acc);
    }
}

// ---------------- launch ----------------
extern "C" void kernel_launch(void* const* d_in, const int* in_sizes, int n_in,
                              void* d_out, int out_size) {
    const float* fg = (const float*)d_in[0];
    const float* cv = (const float*)d_in[1];
    const float* co = (const float*)d_in[2];
    const float* Wc = (const float*)d_in[3];
    const float* bc = (const float*)d_in[4];
    const float* W0 = (const float*)d_in[5];
    const float* b0 = (const float*)d_in[6];
    const float* W1 = (const float*)d_in[7];
    const float* b1 = (const float*)d_in[8];
    const float* W2 = (const float*)d_in[9];
    const float* b2 = (const float*)d_in[10];
    const float* W3 = (const float*)d_in[11];
    const float* b3 = (const float*)d_in[12];
    const float* Wo = (const float*)d_in[13];
    const float* bo = (const float*)d_in[14];
    float* out = (float*)d_out;

    const int smemB = (P * SROW + 2 * KC * HID + 3 * HID + 4) * 4;
    cudaFuncSetAttribute(decoder_kernel,
                         cudaFuncAttributeMaxDynamicSharedMemorySize, smemB);

    prep_ctx_kernel<<<BATCH, HID>>>(cv, Wc, bc);
    prep_w0_kernel<<<K0PAD, HID>>>(W0);
    resize_kernel<32><<<(BATCH * 32 * 32 * C0) / 256, 256>>>(fg);
    resize_kernel<16><<<(BATCH * 16 * 16 * C0) / 256, 256>>>(fg);
    decoder_kernel<<<BATCH * (NPTS / P), 256, smemB>>>(
        fg, co, b0, W1, b1, W2, b2, W3, b3, Wo, bo, out);
}

// round 5
// speedup vs baseline: 2.4111x; 2.4111x over previous
#include <cuda_runtime.h>
#include <cstdint>

#define BATCH    8
#define GH       64
#define C0       64
#define NPTS     16384
#define NFREQ    10
#define HID      256
#define TILE_M   128
#define HSTRIDE  260
#define CHSTRIDE 264

// ---------------- device scratch (static, allocation-free) ----------------
__device__ float g_gamma[BATCH * HID];
__device__ float g_beta [BATCH * HID];
__device__ float g_WT   [4 * HID * HID];   // [layer][k][n], tf32-rounded, K padded/gapped
__device__ float g_lvl1 [BATCH * 32 * 32 * C0];
__device__ float g_lvl2 [BATCH * 16 * 16 * C0];

// ---------------- helpers ----------------
__device__ __forceinline__ uint32_t smem_u32(const void* p) {
    uint32_t a;
    asm("{ .reg .u64 t; cvta.to.shared.u64 t, %1; cvt.u32.u64 %0, t; }" : "=r"(a) : "l"(p));
    return a;
}
__device__ __forceinline__ uint32_t f2tf32(float x) {
    uint32_t r; asm("cvt.rna.tf32.f32 %0, %1;" : "=r"(r) : "f"(x)); return r;
}
__device__ __forceinline__ float tf32r(float x) { return __uint_as_float(f2tf32(x)); }
__device__ __forceinline__ float tanh_fast(float y) {
    float e; asm("ex2.approx.f32 %0, %1;" : "=f"(e) : "f"(y * 2.8853900817779268f));
    float r; asm("rcp.approx.f32 %0, %1;" : "=f"(r) : "f"(e + 1.0f));
    return 1.0f - 2.0f * r;
}
__device__ __forceinline__ float gelu_f(float x) {
    float u = 0.7978845608028654f * fmaf(0.044715f * x, x * x, x);
    return 0.5f * x * (1.0f + tanh_fast(u));
}
__device__ __forceinline__ void cp16(uint32_t saddr, const float* g) {
    asm volatile("cp.async.cg.shared.global [%0], [%1], 16;" :: "r"(saddr), "l"(g));
}
__device__ __forceinline__ void mma_tf32(float* d, const uint32_t* a,
                                         uint32_t b0, uint32_t b1) {
    asm volatile(
        "mma.sync.aligned.m16n8k8.row.col.f32.tf32.tf32.f32 "
        "{%0,%1,%2,%3}, {%4,%5,%6,%7}, {%8,%9}, {%0,%1,%2,%3};"
        : "+f"(d[0]), "+f"(d[1]), "+f"(d[2]), "+f"(d[3])
        : "r"(a[0]), "r"(a[1]), "r"(a[2]), "r"(a[3]), "r"(b0), "r"(b1));
}

// ---------------- prep: FiLM params ----------------
__global__ void prep_ctx_kernel(const float* __restrict__ cv,
                                const float* __restrict__ Wc,
                                const float* __restrict__ bc) {
    int b = blockIdx.x, c = threadIdx.x;
    float g  = bc[c];
    float bt = bc[HID + c];
#pragma unroll 8
    for (int k = 0; k < C0; k++) {
        float v = cv[b * C0 + k];
        g  += v * Wc[k * 2 * HID + c];
        bt += v * Wc[k * 2 * HID + HID + c];
    }
    g_gamma[b * HID + c] = g + 1.0f;
    g_beta [b * HID + c] = bt;
}

// ---------------- prep: tf32-round weights into WT[l][k][n], K padded ------
// K layout (matches h tile): [0..41] posenc, [42..43] zero gap, [44..235]
// features (grid row k-2), [236..255] zero tail. Layers 1-3: direct 256 rows.
__global__ void prep_wt_kernel(const float* __restrict__ W0,
                               const float* __restrict__ W1,
                               const float* __restrict__ W2,
                               const float* __restrict__ W3) {
    int idx = blockIdx.x * blockDim.x + threadIdx.x;   // 4*256*256
    int l = idx >> 16;
    int k = (idx >> 8) & 255;
    int n = idx & 255;
    float v = 0.0f;
    if (l == 0) {
        if (k < 42)                  v = W0[k * HID + n];
        else if (k >= 44 && k < 236) v = W0[(k - 2) * HID + n];
    } else if (l == 1) v = W1[k * HID + n];
    else if (l == 2)   v = W2[k * HID + n];
    else               v = W3[k * HID + n];
    g_WT[idx] = tf32r(v);
}

// ---------------- prep: antialiased bilinear pyramid (jax.image.resize) ----
template <int HL>
__global__ void resize_kernel(const float* __restrict__ src) {
    int idx = blockIdx.x * blockDim.x + threadIdx.x;
    int c = idx & (C0 - 1);
    int v = idx >> 6;
    int x = v % HL;
    int y = (v / HL) % HL;
    int b = v / (HL * HL);

    const float scale = (float)(GH / HL);
    const int   T     = 2 * (GH / HL);

    float sy = (y + 0.5f) * scale - 0.5f;
    float sx = (x + 0.5f) * scale - 0.5f;
    int s0y = (int)floorf(sy - scale) + 1;
    int s0x = (int)floorf(sx - scale) + 1;

    float wy[8], wx[8];
    float sumy = 0.f, sumx = 0.f;
#pragma unroll
    for (int t = 0; t < T; t++) {
        int s = s0y + t;
        float w = 1.0f - fabsf((float)s - sy) / scale;
        w = (s >= 0 && s < GH && w > 0.f) ? w : 0.f;
        wy[t] = w; sumy += w;
        s = s0x + t;
        w = 1.0f - fabsf((float)s - sx) / scale;
        w = (s >= 0 && s < GH && w > 0.f) ? w : 0.f;
        wx[t] = w; sumx += w;
    }
    float inv = 1.0f / (sumy * sumx);

    float acc = 0.f;
#pragma unroll
    for (int a = 0; a < T; a++) {
        if (wy[a] == 0.f) continue;
        const float* row = src + ((((b * GH) + (s0y + a)) * GH) << 6) + c;
        float pacc = 0.f;
#pragma unroll
        for (int t = 0; t < T; t++) {
            if (wx[t] == 0.f) continue;
            pacc += wx[t] * row[(s0x + t) << 6];
        }
        acc += wy[a] * pacc;
    }
    float* dst = (HL == 32) ? g_lvl1 : g_lvl2;
    dst[idx] = acc * inv;
}

// ---------------- weight K-chunk fill: 32 rows x 256 tf32, stride 264 ------
__device__ __forceinline__ void fill_chunk(float* wsm, const float* wt_l,
                                           int c, int tid) {
    uint32_t sb = smem_u32(wsm);
#pragma unroll
    for (int s = 0; s < 4; s++) {
        int u = tid + s * 512;          // 0..2047 16B units
        int row = u >> 6, col4 = u & 63;
        cp16(sb + (uint32_t)(row * CHSTRIDE + col4 * 4) * 4u,
             wt_l + (c * 32 + row) * HID + col4 * 4);
    }
    asm volatile("cp.async.commit_group;" ::: "memory");
}

// ---------------- main fused decoder (mma.sync tf32) ----------------
__global__ __launch_bounds__(512, 1)
void decoder_kernel(const float* __restrict__ fg,
                    const float* __restrict__ coords,
                    const float* __restrict__ b0, const float* __restrict__ b1,
                    const float* __restrict__ b2, const float* __restrict__ b3,
                    const float* __restrict__ Wout, const float* __restrict__ bout,
                    float* __restrict__ out) {
    extern __shared__ float smem[];
    float* wbuf   = smem;                              // 2 * 32 * 264
    float* h_s    = wbuf + 2 * 32 * CHSTRIDE;          // 128 * 260
    float* bias_s = h_s + TILE_M * HSTRIDE;            // 4*256
    float* gam_s  = bias_s + 4 * HID;
    float* bet_s  = gam_s + HID;
    float* wo_s   = bet_s + HID;                       // 768
    float* bo_s   = wo_s + 3 * HID;                    // 4

    const int tid  = threadIdx.x;
    const int wid  = tid >> 5;
    const int lane = tid & 31;
    const int mw   = wid & 3,  nw = wid >> 2;
    const int m0   = mw * 32,  n0 = nw * 64;
    const int r    = lane >> 2, cq = lane & 3;
    const int b    = blockIdx.x >> 7;
    const int n0p  = (blockIdx.x & 127) * TILE_M;

    // prefill layer-0 weight chunks 0,1 (overlaps feature build)
    fill_chunk(wbuf,                 g_WT, 0, tid);
    fill_chunk(wbuf + 32 * CHSTRIDE, g_WT, 1, tid);

    // stage per-CTA params
    if (tid < HID) {
        gam_s[tid]  = g_gamma[b * HID + tid];
        bet_s[tid]  = g_beta [b * HID + tid];
        bias_s[tid]           = b0[tid];
        bias_s[HID + tid]     = b1[tid];
        bias_s[2 * HID + tid] = b2[tid];
        bias_s[3 * HID + tid] = b3[tid];
    }
    if (tid >= 256 && tid < 256 + 192) {
        int i = (tid - 256) * 4;
        *(float4*)(wo_s + i) = *(const float4*)(Wout + i);
    }
    if (tid < 3) bo_s[tid] = bout[tid];

    // ---- build features (tf32-rounded): 4 threads per point ----
    {
        int p = tid >> 2, q = tid & 3;
        float cy = coords[(n0p + p) * 2 + 0];
        float cx = coords[(n0p + p) * 2 + 1];
        float* hp = h_s + p * HSTRIDE;

        if (q == 0) {
            hp[0] = tf32r(cy); hp[1] = tf32r(cx);
            float fr = 3.14159265358979323846f;
#pragma unroll
            for (int f = 0; f < NFREQ; f++) {
                float sv, cvv;
                sincosf(cy * fr, &sv, &cvv);
                hp[2 + 4 * f + 0] = tf32r(sv);
                hp[2 + 4 * f + 2] = tf32r(cvv);
                sincosf(cx * fr, &sv, &cvv);
                hp[2 + 4 * f + 1] = tf32r(sv);
                hp[2 + 4 * f + 3] = tf32r(cvv);
                fr *= 2.0f;
            }
            hp[42] = 0.f; hp[43] = 0.f;
#pragma unroll
            for (int k = 236; k < 256; k++) hp[k] = 0.f;
        }

#pragma unroll
        for (int lvl = 0; lvl < 3; lvl++) {
            int Hl = GH >> lvl;
            const float* G = (lvl == 0) ? fg : ((lvl == 1) ? g_lvl1 : g_lvl2);
            float yf = (cy + 1.0f) * 0.5f * (float)(Hl - 1);
            float xf = (cx + 1.0f) * 0.5f * (float)(Hl - 1);
            float y0f = floorf(yf), x0f = floorf(xf);
            float wy = yf - y0f, wx = xf - x0f;
            int y0 = min(max((int)y0f, 0), Hl - 1);
            int x0 = min(max((int)x0f, 0), Hl - 1);
            int y1 = min(y0 + 1, Hl - 1);
            int x1 = min(x0 + 1, Hl - 1);
            const float* p00 = G + ((((b * Hl) + y0) * Hl + x0) << 6);
            const float* p01 = G + ((((b * Hl) + y0) * Hl + x1) << 6);
            const float* p10 = G + ((((b * Hl) + y1) * Hl + x0) << 6);
            const float* p11 = G + ((((b * Hl) + y1) * Hl + x1) << 6);
            float omx = 1.0f - wx, omy = 1.0f - wy;
            float* dst = hp + 44 + lvl * 64 + q * 16;
#pragma unroll
            for (int cc = 0; cc < 4; cc++) {
                int c = q * 16 + cc * 4;
                float4 v00 = *(const float4*)(p00 + c);
                float4 v01 = *(const float4*)(p01 + c);
                float4 v10 = *(const float4*)(p10 + c);
                float4 v11 = *(const float4*)(p11 + c);
                dst[cc*4+0] = tf32r((v00.x * omx + v01.x * wx) * omy + (v10.x * omx + v11.x * wx) * wy);
                dst[cc*4+1] = tf32r((v00.y * omx + v01.y * wx) * omy + (v10.y * omx + v11.y * wx) * wy);
                dst[cc*4+2] = tf32r((v00.z * omx + v01.z * wx) * omy + (v10.z * omx + v11.z * wx) * wy);
                dst[cc*4+3] = tf32r((v00.w * omx + v01.w * wx) * omy + (v10.w * omx + v11.w * wx) * wy);
            }
        }
    }
    __syncthreads();

    // ---- 4 FiLM'd MLP layers on tensor cores ----
    for (int l = 0; l < 4; l++) {
        const float* WTl = g_WT + l * (HID * HID);

        float acc[2][8][4];
#pragma unroll
        for (int i = 0; i < 2; i++)
#pragma unroll
            for (int j = 0; j < 8; j++)
#pragma unroll
                for (int v = 0; v < 4; v++) acc[i][j][v] = 0.f;

        for (int c = 0; c < 8; c++) {
            if (c < 7) asm volatile("cp.async.wait_group 1;" ::: "memory");
            else       asm volatile("cp.async.wait_group 0;" ::: "memory");
            __syncthreads();

            const float* wb = wbuf + (c & 1) * (32 * CHSTRIDE);
#pragma unroll
            for (int ks = 0; ks < 4; ks++) {
                const int kg = c * 32 + ks * 8;
                uint32_t a[2][4];
                const float* ha = h_s + (m0 + r) * HSTRIDE + kg + cq;
#pragma unroll
                for (int mt = 0; mt < 2; mt++) {
                    const float* hm = ha + mt * 16 * HSTRIDE;
                    a[mt][0] = __float_as_uint(hm[0]);
                    a[mt][1] = __float_as_uint(hm[8 * HSTRIDE]);
                    a[mt][2] = __float_as_uint(hm[4]);
                    a[mt][3] = __float_as_uint(hm[8 * HSTRIDE + 4]);
                }
                const float* wr = wb + (ks * 8 + cq) * CHSTRIDE + n0 + r;
#pragma unroll
                for (int nt = 0; nt < 8; nt++) {
                    uint32_t bb0 = __float_as_uint(wr[nt * 8]);
                    uint32_t bb1 = __float_as_uint(wr[4 * CHSTRIDE + nt * 8]);
                    mma_tf32(acc[0][nt], a[0], bb0, bb1);
                    mma_tf32(acc[1][nt], a[1], bb0, bb1);
                }
            }
            __syncthreads();
            if (c < 6) fill_chunk(wbuf + (c & 1) * (32 * CHSTRIDE), WTl, c + 2, tid);
        }

        // ---- epilogue: bias + FiLM + gelu, write back (tf32-rounded) ----
#pragma unroll
        for (int nt = 0; nt < 8; nt++) {
            int n = n0 + nt * 8 + 2 * cq;
            float g0 = gam_s[n],     g1 = gam_s[n + 1];
            float be0 = bet_s[n],    be1 = bet_s[n + 1];
            float bi0 = bias_s[l * HID + n], bi1 = bias_s[l * HID + n + 1];
#pragma unroll
            for (int mt = 0; mt < 2; mt++) {
                int p0 = m0 + mt * 16 + r;
                float v0 = (acc[mt][nt][0] + bi0) * g0 + be0;
                float v1 = (acc[mt][nt][1] + bi1) * g1 + be1;
                float v2 = (acc[mt][nt][2] + bi0) * g0 + be0;
                float v3 = (acc[mt][nt][3] + bi1) * g1 + be1;
                *(float2*)(h_s + p0 * HSTRIDE + n) =
                    make_float2(tf32r(gelu_f(v0)), tf32r(gelu_f(v1)));
                *(float2*)(h_s + (p0 + 8) * HSTRIDE + n) =
                    make_float2(tf32r(gelu_f(v2)), tf32r(gelu_f(v3)));
            }
        }
        __syncthreads();

        if (l < 3) {
            const float* WTn = g_WT + (l + 1) * (HID * HID);
            fill_chunk(wbuf,                 WTn, 0, tid);
            fill_chunk(wbuf + 32 * CHSTRIDE, WTn, 1, tid);
        }
    }

    // ---- output head: tanh(h @ Wout + bout) ----
    if (tid < 384) {
        int p = tid & 127, o = tid >> 7;
        float acc = bo_s[o];
        const float* hp = h_s + p * HSTRIDE;
#pragma unroll 8
        for (int k = 0; k < HID; k++) acc += hp[k] * wo_s[k * 3 + o];
        out[((size_t)b * NPTS + n0p + p) * 3 + o] = tanh_fast(acc);
    }
}

// ---------------- launch ----------------
extern "C" void kernel_launch(void* const* d_in, const int* in_sizes, int n_in,
                              void* d_out, int out_size) {
    const float* fg = (const float*)d_in[0];
    const float* cv = (const float*)d_in[1];
    const float* co = (const float*)d_in[2];
    const float* Wc = (const float*)d_in[3];
    const float* bc = (const float*)d_in[4];
    const float* W0 = (const float*)d_in[5];
    const float* b0 = (const float*)d_in[6];
    const float* W1 = (const float*)d_in[7];
    const float* b1 = (const float*)d_in[8];
    const float* W2 = (const float*)d_in[9];
    const float* b2 = (const float*)d_in[10];
    const float* W3 = (const float*)d_in[11];
    const float* b3 = (const float*)d_in[12];
    const float* Wo = (const float*)d_in[13];
    const float* bo = (const float*)d_in[14];
    float* out = (float*)d_out;

    const int smemB = (2 * 32 * CHSTRIDE + TILE_M * HSTRIDE +
                       4 * HID + HID + HID + 3 * HID + 4) * 4;
    cudaFuncSetAttribute(decoder_kernel,
                         cudaFuncAttributeMaxDynamicSharedMemorySize, smemB);

    prep_ctx_kernel<<<BATCH, HID>>>(cv, Wc, bc);
    prep_wt_kernel<<<(4 * HID * HID) / 256, 256>>>(W0, W1, W2, W3);
    resize_kernel<32><<<(BATCH * 32 * 32 * C0) / 256, 256>>>(fg);
    resize_kernel<16><<<(BATCH * 16 * 16 * C0) / 256, 256>>>(fg);
    decoder_kernel<<<BATCH * (NPTS / TILE_M), 512, smemB>>>(
        fg, co, b0, b1, b2, b3, Wo, bo, out);
}